// round 9
// baseline (speedup 1.0000x reference)
#include <cuda_runtime.h>
#include <cuda_bf16.h>

// Problem constants (match reference)
#define HH 512
#define WW 512
#define RR 4
#define BB 2
#define PP 65536
#define CC 8
#define NPTS (BB * PP)
#define NPIX (BB * HH * WW)

// Tiling: 8 x 8 pixel tiles; ONE warp per tile, TWO pixels per thread
// (vertical pair: same column, rows py and py+4).
#define TW 8
#define TH 8
#define TILES_X (WW / TW)              // 64
#define TILES_Y (HH / TH)              // 64
#define TILES_IMG (TILES_X * TILES_Y)  // 4096
#define NTILES (BB * TILES_IMG)        // 8192
#define CAP 160                        // per-tile capacity (mean ~60)
#define CHUNK 32                       // candidates staged per warp round

__device__ int g_cnt[NTILES];          // zero at load; gather resets after use
__device__ int g_list[NTILES * CAP];

// NDC coordinate of a pixel center — the single validated formula.
#define NDC(p) __fadd_rn(__fmul_rn(2.0f, (float)(p)) / 511.0f, -1.0f)

// ---------------------------------------------------------------------------
__device__ __forceinline__ unsigned long long pack2(float a, float b) {
    unsigned long long r;
    asm("mov.b64 %0, {%1, %2};" : "=l"(r) : "r"(__float_as_uint(a)), "r"(__float_as_uint(b)));
    return r;
}
__device__ __forceinline__ void unpack2(unsigned long long v, float& a, float& b) {
    unsigned int lo, hi;
    asm("mov.b64 {%0, %1}, %2;" : "=r"(lo), "=r"(hi) : "l"(v));
    a = __uint_as_float(lo);
    b = __uint_as_float(hi);
}
__device__ __forceinline__ void ffma2(unsigned long long& acc,
                                      unsigned long long a,
                                      unsigned long long b) {
    asm("fma.rn.f32x2 %0, %1, %2, %0;" : "+l"(acc) : "l"(a), "l"(b));
}

// ---------------------------------------------------------------------------
// Bin each valid point into the 8x8 tiles its disc can actually touch
// (box spans exactly <=2x2 tiles; circle-vs-tile prefilter trims corners).
// Falsely-kept candidates are harmless (gather re-tests exactly);
// falsely-dropped impossible (continuous min distance <= discrete, margin
// covers rounding).
__global__ void __launch_bounds__(256) k_bin(const float* __restrict__ pts,
                                             const float* __restrict__ mr_ptr) {
    int i = blockIdx.x * blockDim.x + threadIdx.x;   // NPTS divisible by 256
    float x = pts[3 * i + 0];
    float y = pts[3 * i + 1];
    float z = pts[3 * i + 2];
    if (!(z > 0.1f && z < 10.0f)) return;

    int cx = (int)rintf((x + 1.0f) * 0.5f * 511.0f);
    int cy = (int)rintf((y + 1.0f) * 0.5f * 511.0f);
    int px0 = max(cx - RR, 0), px1 = min(cx + RR, WW - 1);
    int py0 = max(cy - RR, 0), py1 = min(cy + RR, HH - 1);
    if (px0 > px1 || py0 > py1) return;

    float mr = __ldg(mr_ptr);
    float r2m = mr * mr * 1.000002f + 1e-12f;        // conservative margin

    int tx0 = px0 >> 3, tx1 = px1 >> 3;              // TW = 8
    int ty0 = py0 >> 3, ty1 = py1 >> 3;              // TH = 8
    int tb = (i >= PP) ? TILES_IMG : 0;

    for (int ty = ty0; ty <= ty1; ++ty) {
        float ly = NDC(ty * TH), hy = NDC(ty * TH + (TH - 1));
        float cyn = fminf(fmaxf(y, ly), hy);
        float ddy = cyn - y;
        float dy2 = ddy * ddy;
        for (int tx = tx0; tx <= tx1; ++tx) {
            float lx = NDC(tx * TW), hx = NDC(tx * TW + (TW - 1));
            float cxn = fminf(fmaxf(x, lx), hx);
            float ddx = cxn - x;
            if (ddx * ddx + dy2 <= r2m) {
                int t = tb + ty * TILES_X + tx;
                int slot = atomicAdd(&g_cnt[t], 1);
                if (slot < CAP) g_list[t * CAP + slot] = i;
            }
        }
    }
}

// ---------------------------------------------------------------------------
// Gather: one warp per 8x8 tile, 2 pixels per thread (same column -> dx and
// the candidate LDS broadcasts are shared). Branchless f32x2 inner loop
// (validated R7/R8). Stabilizer-free weights w' = ws*exp(-2z) — exact
// cancellation (R2-R8). Fragment math bit-identical to R7/R8.
__global__ void __launch_bounds__(64) k_gather(
        const float* __restrict__ pts,
        const float* __restrict__ feat,
        const float* __restrict__ sig,
        const float* __restrict__ mr_ptr,
        float* __restrict__ out) {
    __shared__ float4 sA[2][CHUNK];                  // x, y, inv2s2, unused
    __shared__ unsigned long long sEZ[2][CHUNK];     // (ez, ez*z)
    __shared__ ulonglong2 sF[2][CHUNK * 2];          // ez*f packed as 4x f32x2

    int warp = threadIdx.x >> 5;
    int lane = threadIdx.x & 31;
    int t = blockIdx.x * 2 + warp;

    int b = t >> 12;                                 // / TILES_IMG (4096)
    int r = t & (TILES_IMG - 1);
    int ty = r >> 6;                                 // / TILES_X (64)
    int tx = r & (TILES_X - 1);

    int px  = tx * TW + (lane & (TW - 1));
    int py0 = ty * TH + (lane >> 3);                 // rows 0..3
    int py1 = py0 + 4;                               // rows 4..7

    float qxn  = NDC(px);
    float qyn0 = NDC(py0);
    float qyn1 = NDC(py1);

    float mr = __ldg(mr_ptr);
    float r2 = mr * mr;

    int cnt = g_cnt[t];
    if (cnt > CAP) cnt = CAP;

    const float4* ff = (const float4*)feat;

    float accWS0 = 0.f, accWS1 = 0.f;
    unsigned long long aW0 = 0ull, aW1 = 0ull;       // (accW, accWZ)
    unsigned long long p01 = 0ull, p23 = 0ull, p45 = 0ull, p67 = 0ull;
    unsigned long long q01 = 0ull, q23 = 0ull, q45 = 0ull, q67 = 0ull;

    for (int c0 = 0; c0 < cnt; c0 += CHUNK) {
        int m = min(CHUNK, cnt - c0);
        if (lane < m) {
            int j = g_list[t * CAP + c0 + lane];
            float x = pts[3 * j + 0];
            float y = pts[3 * j + 1];
            float z = pts[3 * j + 2];
            float s = sig[j];
            float sinv = 1.0f / (2.0f * s * s);
            float ez = __expf(-2.0f * z);            // GAMMA = 0.5
            sA[warp][lane] = make_float4(x, y, sinv, 0.0f);
            sEZ[warp][lane] = pack2(ez, ez * z);
            float4 fa = ff[2 * j + 0];
            float4 fb = ff[2 * j + 1];
            sF[warp][2 * lane + 0] = make_ulonglong2(pack2(ez * fa.x, ez * fa.y),
                                                     pack2(ez * fa.z, ez * fa.w));
            sF[warp][2 * lane + 1] = make_ulonglong2(pack2(ez * fb.x, ez * fb.y),
                                                     pack2(ez * fb.z, ez * fb.w));
        }
        __syncwarp();

#pragma unroll 2
        for (int k = 0; k < m; ++k) {
            float4 A = sA[warp][k];
            unsigned long long ez2 = sEZ[warp][k];
            ulonglong2 f01 = sF[warp][2 * k + 0];
            ulonglong2 f23 = sF[warp][2 * k + 1];

            float dx  = __fadd_rn(qxn, -A.x);
            float dx2 = __fmul_rn(dx, dx);

            // pixel 0
            float dy0 = __fadd_rn(qyn0, -A.y);
            float d20 = __fadd_rn(dx2, __fmul_rn(dy0, dy0));
            float e0  = __expf(-d20 * A.z);
            float ws0 = (d20 <= r2) ? e0 : 0.0f;
            accWS0 += ws0;
            unsigned long long w20;
            asm("mov.b64 %0, {%1, %1};" : "=l"(w20) : "r"(__float_as_uint(ws0)));
            ffma2(aW0, w20, ez2);
            ffma2(p01, w20, f01.x);
            ffma2(p23, w20, f01.y);
            ffma2(p45, w20, f23.x);
            ffma2(p67, w20, f23.y);

            // pixel 1 (same column, +4 rows)
            float dy1 = __fadd_rn(qyn1, -A.y);
            float d21 = __fadd_rn(dx2, __fmul_rn(dy1, dy1));
            float e1  = __expf(-d21 * A.z);
            float ws1 = (d21 <= r2) ? e1 : 0.0f;
            accWS1 += ws1;
            unsigned long long w21;
            asm("mov.b64 %0, {%1, %1};" : "=l"(w21) : "r"(__float_as_uint(ws1)));
            ffma2(aW1, w21, ez2);
            ffma2(q01, w21, f01.x);
            ffma2(q23, w21, f01.y);
            ffma2(q45, w21, f23.x);
            ffma2(q67, w21, f23.y);
        }
        __syncwarp();
    }

    float4* col = (float4*)out;
    int pixbase = b * (HH * WW) + px;

    {   // pixel 0
        float accW, accWZ, f0, f1, f2, f3, f4v, f5, f6, f7;
        unpack2(aW0, accW, accWZ);
        unpack2(p01, f0, f1);  unpack2(p23, f2, f3);
        unpack2(p45, f4v, f5); unpack2(p67, f6, f7);
        int pix = pixbase + py0 * WW;
        float inv = (accW > 0.0f) ? (1.0f / accW) : 0.0f;
        col[2 * pix + 0] = make_float4(f0 * inv, f1 * inv, f2 * inv, f3 * inv);
        col[2 * pix + 1] = make_float4(f4v * inv, f5 * inv, f6 * inv, f7 * inv);
        out[NPIX * CC + pix]        = accWZ * inv;
        out[NPIX * CC + NPIX + pix] = 1.0f - expf(-accWS0);
    }
    {   // pixel 1
        float accW, accWZ, f0, f1, f2, f3, f4v, f5, f6, f7;
        unpack2(aW1, accW, accWZ);
        unpack2(q01, f0, f1);  unpack2(q23, f2, f3);
        unpack2(q45, f4v, f5); unpack2(q67, f6, f7);
        int pix = pixbase + py1 * WW;
        float inv = (accW > 0.0f) ? (1.0f / accW) : 0.0f;
        col[2 * pix + 0] = make_float4(f0 * inv, f1 * inv, f2 * inv, f3 * inv);
        col[2 * pix + 1] = make_float4(f4v * inv, f5 * inv, f6 * inv, f7 * inv);
        out[NPIX * CC + pix]        = accWZ * inv;
        out[NPIX * CC + NPIX + pix] = 1.0f - expf(-accWS1);
    }

    // Reset counter for next graph replay (all lanes of this warp already
    // read g_cnt[t] above).
    if (lane == 0) g_cnt[t] = 0;
}

// ---------------------------------------------------------------------------
extern "C" void kernel_launch(void* const* d_in, const int* in_sizes, int n_in,
                              void* d_out, int out_size) {
    const float* pts  = (const float*)d_in[0];  // [B,P,3]
    const float* feat = (const float*)d_in[1];  // [B,P,8]
    const float* sig  = (const float*)d_in[2];  // [B,P]
    const float* mr   = (const float*)d_in[3];  // scalar
    float* out = (float*)d_out;

    k_bin   <<<NPTS / 256, 256>>>(pts, mr);
    k_gather<<<NTILES / 2, 64>>>(pts, feat, sig, mr, out);
}

// round 10
// speedup vs baseline: 1.0677x; 1.0677x over previous
#include <cuda_runtime.h>
#include <cuda_bf16.h>

// Problem constants (match reference)
#define HH 512
#define WW 512
#define RR 4
#define BB 2
#define PP 65536
#define CC 8
#define NPTS (BB * PP)
#define NPIX (BB * HH * WW)

// Tiling: 8 x 8 pixel tiles; ONE warp per tile, TWO pixels per thread
// (vertical pair: same column, rows py and py+4).
#define TW 8
#define TH 8
#define TILES_X (WW / TW)              // 64
#define TILES_Y (HH / TH)              // 64
#define TILES_IMG (TILES_X * TILES_Y)  // 4096
#define NTILES (BB * TILES_IMG)        // 8192
#define CAP 160                        // per-tile capacity (mean ~60)
#define CHUNK 32                       // candidates staged per warp round

#define LOG2E 1.4426950408889634f

__device__ int g_cnt[NTILES];          // zero at load; gather resets after use
__device__ int g_list[NTILES * CAP];

// NDC coordinate of a pixel center — the single validated formula.
#define NDC(p) __fadd_rn(__fmul_rn(2.0f, (float)(p)) / 511.0f, -1.0f)

// ---------------------------------------------------------------------------
__device__ __forceinline__ unsigned long long pack2(float a, float b) {
    unsigned long long r;
    asm("mov.b64 %0, {%1, %2};" : "=l"(r) : "r"(__float_as_uint(a)), "r"(__float_as_uint(b)));
    return r;
}
__device__ __forceinline__ void unpack2(unsigned long long v, float& a, float& b) {
    unsigned int lo, hi;
    asm("mov.b64 {%0, %1}, %2;" : "=r"(lo), "=r"(hi) : "l"(v));
    a = __uint_as_float(lo);
    b = __uint_as_float(hi);
}
__device__ __forceinline__ void ffma2(unsigned long long& acc,
                                      unsigned long long a,
                                      unsigned long long b) {
    asm("fma.rn.f32x2 %0, %1, %2, %0;" : "+l"(acc) : "l"(a), "l"(b));
}
__device__ __forceinline__ float ex2(float x) {
    float r;
    asm("ex2.approx.f32 %0, %1;" : "=f"(r) : "f"(x));
    return r;
}

// ---------------------------------------------------------------------------
// Bin each valid point into the 8x8 tiles its disc can actually touch
// (box spans <=2x2 tiles; circle-vs-tile prefilter trims corners).
// Falsely-kept candidates are harmless (gather re-tests exactly).
__global__ void __launch_bounds__(256) k_bin(const float* __restrict__ pts,
                                             const float* __restrict__ mr_ptr) {
    int i = blockIdx.x * blockDim.x + threadIdx.x;   // NPTS divisible by 256
    float x = pts[3 * i + 0];
    float y = pts[3 * i + 1];
    float z = pts[3 * i + 2];
    if (!(z > 0.1f && z < 10.0f)) return;

    int cx = (int)rintf((x + 1.0f) * 0.5f * 511.0f);
    int cy = (int)rintf((y + 1.0f) * 0.5f * 511.0f);
    int px0 = max(cx - RR, 0), px1 = min(cx + RR, WW - 1);
    int py0 = max(cy - RR, 0), py1 = min(cy + RR, HH - 1);
    if (px0 > px1 || py0 > py1) return;

    float mr = __ldg(mr_ptr);
    float r2m = mr * mr * 1.000002f + 1e-12f;        // conservative margin

    int tx0 = px0 >> 3, tx1 = px1 >> 3;              // TW = 8
    int ty0 = py0 >> 3, ty1 = py1 >> 3;              // TH = 8
    int tb = (i >= PP) ? TILES_IMG : 0;

    for (int ty = ty0; ty <= ty1; ++ty) {
        float ly = NDC(ty * TH), hy = NDC(ty * TH + (TH - 1));
        float cyn = fminf(fmaxf(y, ly), hy);
        float ddy = cyn - y;
        float dy2 = ddy * ddy;
        for (int tx = tx0; tx <= tx1; ++tx) {
            float lx = NDC(tx * TW), hx = NDC(tx * TW + (TW - 1));
            float cxn = fminf(fmaxf(x, lx), hx);
            float ddx = cxn - x;
            if (ddx * ddx + dy2 <= r2m) {
                int t = tb + ty * TILES_X + tx;
                int slot = atomicAdd(&g_cnt[t], 1);
                if (slot < CAP) g_list[t * CAP + slot] = i;
            }
        }
    }
}

// ---------------------------------------------------------------------------
// Gather: one warp per 8x8 tile, 2 pixels per thread. Branchless f32x2 inner
// loop with a fixed-trip fully-addressable fast path (immediate LDS offsets).
// Cull math (NDC/d2/compare) bit-identical to R1-R9. ws uses ex2 with log2e
// folded into the staged coefficient (~1 ulp smooth perturbation; cancels in
// the ratio). Stabilizer-free weights w' = ws*exp(-2z) (exact, R2-R9).
__global__ void __launch_bounds__(64, 16) k_gather(
        const float* __restrict__ pts,
        const float* __restrict__ feat,
        const float* __restrict__ sig,
        const float* __restrict__ mr_ptr,
        float* __restrict__ out) {
    __shared__ float4 sA[2][CHUNK];                  // x, y, -inv2s2*log2e, pad
    __shared__ unsigned long long sEZ[2][CHUNK];     // (ez, ez*z)
    __shared__ ulonglong2 sF[2][CHUNK * 2];          // ez*f packed as 4x f32x2

    int warp = threadIdx.x >> 5;
    int lane = threadIdx.x & 31;
    int t = blockIdx.x * 2 + warp;

    int b = t >> 12;                                 // / TILES_IMG (4096)
    int r = t & (TILES_IMG - 1);
    int ty = r >> 6;                                 // / TILES_X (64)
    int tx = r & (TILES_X - 1);

    int px  = tx * TW + (lane & (TW - 1));
    int py0 = ty * TH + (lane >> 3);                 // rows 0..3
    int py1 = py0 + 4;                               // rows 4..7

    float qxn  = NDC(px);
    float qyn0 = NDC(py0);
    float qyn1 = NDC(py1);

    float mr = __ldg(mr_ptr);
    float r2 = mr * mr;

    int cnt = g_cnt[t];
    if (cnt > CAP) cnt = CAP;

    const float4* ff = (const float4*)feat;

    float accWS0 = 0.f, accWS1 = 0.f;
    unsigned long long aW0 = 0ull, aW1 = 0ull;       // (accW, accWZ)
    unsigned long long p01 = 0ull, p23 = 0ull, p45 = 0ull, p67 = 0ull;
    unsigned long long q01 = 0ull, q23 = 0ull, q45 = 0ull, q67 = 0ull;

#define BODY(K)                                                               \
    {                                                                         \
        float4 A = sA[warp][(K)];                                             \
        unsigned long long ez2 = sEZ[warp][(K)];                              \
        ulonglong2 f01 = sF[warp][2 * (K) + 0];                               \
        ulonglong2 f23 = sF[warp][2 * (K) + 1];                               \
        float dx  = __fadd_rn(qxn, -A.x);                                     \
        float dx2 = __fmul_rn(dx, dx);                                        \
        float dy0 = __fadd_rn(qyn0, -A.y);                                    \
        float d20 = __fadd_rn(dx2, __fmul_rn(dy0, dy0));                      \
        float e0  = ex2(d20 * A.z);                                           \
        float ws0 = (d20 <= r2) ? e0 : 0.0f;                                  \
        accWS0 += ws0;                                                        \
        unsigned long long w20;                                               \
        asm("mov.b64 %0, {%1, %1};" : "=l"(w20) : "r"(__float_as_uint(ws0))); \
        ffma2(aW0, w20, ez2);                                                 \
        ffma2(p01, w20, f01.x);                                               \
        ffma2(p23, w20, f01.y);                                               \
        ffma2(p45, w20, f23.x);                                               \
        ffma2(p67, w20, f23.y);                                               \
        float dy1 = __fadd_rn(qyn1, -A.y);                                    \
        float d21 = __fadd_rn(dx2, __fmul_rn(dy1, dy1));                      \
        float e1  = ex2(d21 * A.z);                                           \
        float ws1 = (d21 <= r2) ? e1 : 0.0f;                                  \
        accWS1 += ws1;                                                        \
        unsigned long long w21;                                               \
        asm("mov.b64 %0, {%1, %1};" : "=l"(w21) : "r"(__float_as_uint(ws1))); \
        ffma2(aW1, w21, ez2);                                                 \
        ffma2(q01, w21, f01.x);                                               \
        ffma2(q23, w21, f01.y);                                               \
        ffma2(q45, w21, f23.x);                                               \
        ffma2(q67, w21, f23.y);                                               \
    }

    for (int c0 = 0; c0 < cnt; c0 += CHUNK) {
        int m = min(CHUNK, cnt - c0);
        if (lane < m) {
            int j = g_list[t * CAP + c0 + lane];
            float x = pts[3 * j + 0];
            float y = pts[3 * j + 1];
            float z = pts[3 * j + 2];
            float s = sig[j];
            // ex2 coefficient: -(1/(2 s^2)) * log2(e)  (ws = 2^(d2*coef))
            float coef = -(1.0f / (2.0f * s * s)) * LOG2E;
            float ez = __expf(-2.0f * z);            // GAMMA = 0.5
            sA[warp][lane] = make_float4(x, y, coef, 0.0f);
            sEZ[warp][lane] = pack2(ez, ez * z);
            float4 fa = ff[2 * j + 0];
            float4 fb = ff[2 * j + 1];
            sF[warp][2 * lane + 0] = make_ulonglong2(pack2(ez * fa.x, ez * fa.y),
                                                     pack2(ez * fa.z, ez * fa.w));
            sF[warp][2 * lane + 1] = make_ulonglong2(pack2(ez * fb.x, ez * fb.y),
                                                     pack2(ez * fb.z, ez * fb.w));
        }
        __syncwarp();

        if (m == CHUNK) {
            // Fixed trip count -> immediate LDS offsets, minimal loop overhead.
#pragma unroll 8
            for (int k = 0; k < CHUNK; ++k) BODY(k);
        } else {
            for (int k = 0; k < m; ++k) BODY(k);
        }
        __syncwarp();
    }
#undef BODY

    float4* col = (float4*)out;
    int pixbase = b * (HH * WW) + px;

    {   // pixel 0
        float accW, accWZ, f0, f1, f2, f3, f4v, f5, f6, f7;
        unpack2(aW0, accW, accWZ);
        unpack2(p01, f0, f1);  unpack2(p23, f2, f3);
        unpack2(p45, f4v, f5); unpack2(p67, f6, f7);
        int pix = pixbase + py0 * WW;
        float inv = (accW > 0.0f) ? (1.0f / accW) : 0.0f;
        col[2 * pix + 0] = make_float4(f0 * inv, f1 * inv, f2 * inv, f3 * inv);
        col[2 * pix + 1] = make_float4(f4v * inv, f5 * inv, f6 * inv, f7 * inv);
        out[NPIX * CC + pix]        = accWZ * inv;
        out[NPIX * CC + NPIX + pix] = 1.0f - expf(-accWS0);
    }
    {   // pixel 1
        float accW, accWZ, f0, f1, f2, f3, f4v, f5, f6, f7;
        unpack2(aW1, accW, accWZ);
        unpack2(q01, f0, f1);  unpack2(q23, f2, f3);
        unpack2(q45, f4v, f5); unpack2(q67, f6, f7);
        int pix = pixbase + py1 * WW;
        float inv = (accW > 0.0f) ? (1.0f / accW) : 0.0f;
        col[2 * pix + 0] = make_float4(f0 * inv, f1 * inv, f2 * inv, f3 * inv);
        col[2 * pix + 1] = make_float4(f4v * inv, f5 * inv, f6 * inv, f7 * inv);
        out[NPIX * CC + pix]        = accWZ * inv;
        out[NPIX * CC + NPIX + pix] = 1.0f - expf(-accWS1);
    }

    // Reset counter for next graph replay (all lanes of this warp already
    // read g_cnt[t] above).
    if (lane == 0) g_cnt[t] = 0;
}

// ---------------------------------------------------------------------------
extern "C" void kernel_launch(void* const* d_in, const int* in_sizes, int n_in,
                              void* d_out, int out_size) {
    const float* pts  = (const float*)d_in[0];  // [B,P,3]
    const float* feat = (const float*)d_in[1];  // [B,P,8]
    const float* sig  = (const float*)d_in[2];  // [B,P]
    const float* mr   = (const float*)d_in[3];  // scalar
    float* out = (float*)d_out;

    k_bin   <<<NPTS / 256, 256>>>(pts, mr);
    k_gather<<<NTILES / 2, 64>>>(pts, feat, sig, mr, out);
}

// round 11
// speedup vs baseline: 1.0842x; 1.0154x over previous
#include <cuda_runtime.h>
#include <cuda_bf16.h>

// Problem constants (match reference)
#define HH 512
#define WW 512
#define RR 4
#define BB 2
#define PP 65536
#define CC 8
#define NPTS (BB * PP)
#define NPIX (BB * HH * WW)

// Tiling: 8 x 8 pixel tiles; ONE warp per tile, TWO pixels per thread
// (vertical pair). CTA = 128 threads = 4 warps = 4 tiles.
#define TW 8
#define TH 8
#define TILES_X (WW / TW)              // 64
#define TILES_Y (HH / TH)              // 64
#define TILES_IMG (TILES_X * TILES_Y)  // 4096
#define NTILES (BB * TILES_IMG)        // 8192
#define CAP 160                        // per-tile capacity (mean ~55)
#define CHUNK 32                       // candidates staged per warp round

#define LOG2E 1.4426950408889634f

__device__ int g_cnt[NTILES];          // zero at load; gather resets after use
__device__ int g_list[NTILES * CAP];

// NDC coordinate of a pixel center — the single validated formula.
#define NDC(p) __fadd_rn(__fmul_rn(2.0f, (float)(p)) / 511.0f, -1.0f)

// ---------------------------------------------------------------------------
__device__ __forceinline__ unsigned long long pack2(float a, float b) {
    unsigned long long r;
    asm("mov.b64 %0, {%1, %2};" : "=l"(r) : "r"(__float_as_uint(a)), "r"(__float_as_uint(b)));
    return r;
}
__device__ __forceinline__ void unpack2(unsigned long long v, float& a, float& b) {
    unsigned int lo, hi;
    asm("mov.b64 {%0, %1}, %2;" : "=r"(lo), "=r"(hi) : "l"(v));
    a = __uint_as_float(lo);
    b = __uint_as_float(hi);
}
__device__ __forceinline__ void ffma2(unsigned long long& acc,
                                      unsigned long long a,
                                      unsigned long long b) {
    asm("fma.rn.f32x2 %0, %1, %2, %0;" : "+l"(acc) : "l"(a), "l"(b));
}
__device__ __forceinline__ float ex2(float x) {
    float r;
    asm("ex2.approx.f32 %0, %1;" : "=f"(r) : "f"(x));
    return r;
}

// ---------------------------------------------------------------------------
// Bin each valid point into the 8x8 tiles its disc can touch, using the
// EXACT discrete prefilter: the minimum d2 over the tile's pixel centers is
// separable -> attained at qx* = clamp(cx, tile), qy* = clamp(cy, tile).
// Computed with arithmetic bit-identical to gather's cull, so "d2* > r2"
// exactly implies no pixel of the tile passes (fadd/square are monotone and
// NDC spacing 3.9e-3 >> ulp). No margin needed. Falsely-kept candidates are
// impossible to be falsely-dropped; kept ones are re-tested exactly in gather.
__global__ void __launch_bounds__(256) k_bin(const float* __restrict__ pts,
                                             const float* __restrict__ mr_ptr) {
    int i = blockIdx.x * blockDim.x + threadIdx.x;   // NPTS divisible by 256
    float x = pts[3 * i + 0];
    float y = pts[3 * i + 1];
    float z = pts[3 * i + 2];
    if (!(z > 0.1f && z < 10.0f)) return;

    int cx = (int)rintf((x + 1.0f) * 0.5f * 511.0f);
    int cy = (int)rintf((y + 1.0f) * 0.5f * 511.0f);
    int px0 = max(cx - RR, 0), px1 = min(cx + RR, WW - 1);
    int py0 = max(cy - RR, 0), py1 = min(cy + RR, HH - 1);
    if (px0 > px1 || py0 > py1) return;

    float mr = __ldg(mr_ptr);
    float r2 = mr * mr;

    int tx0 = px0 >> 3, tx1 = px1 >> 3;              // TW = 8
    int ty0 = py0 >> 3, ty1 = py1 >> 3;              // TH = 8
    int tb = (i >= PP) ? TILES_IMG : 0;

    for (int ty = ty0; ty <= ty1; ++ty) {
        int qys = min(max(cy, ty * TH), ty * TH + (TH - 1));   // nearest row
        float dy = __fadd_rn(NDC(qys), -y);
        float dy2 = __fmul_rn(dy, dy);
        for (int tx = tx0; tx <= tx1; ++tx) {
            int qxs = min(max(cx, tx * TW), tx * TW + (TW - 1)); // nearest col
            float dx = __fadd_rn(NDC(qxs), -x);
            float d2s = __fadd_rn(__fmul_rn(dx, dx), dy2);       // exact min d2
            if (d2s <= r2) {
                int t = tb + ty * TILES_X + tx;
                int slot = atomicAdd(&g_cnt[t], 1);
                if (slot < CAP) g_list[t * CAP + slot] = i;
            }
        }
    }
}

// ---------------------------------------------------------------------------
// Gather: 4 warps per CTA, each warp owns one 8x8 tile; 2 pixels per thread.
// Branchless f32x2 inner loop; immediate-offset LDS for full chunks, stepped
// groups-of-8 (register base + immediate) for partial chunks, dynamic tail <8.
// Cull math (NDC/d2/compare) bit-identical to R1-R10. ws = 2^(d2*coef) with
// log2e folded into the staged coefficient (validated R10). Stabilizer-free
// weights w' = ws*exp(-2z) (exact cancellation, R2-R10).
__global__ void __launch_bounds__(128, 8) k_gather(
        const float* __restrict__ pts,
        const float* __restrict__ feat,
        const float* __restrict__ sig,
        const float* __restrict__ mr_ptr,
        float* __restrict__ out) {
    __shared__ float4 sA[4][CHUNK];                  // x, y, -inv2s2*log2e, pad
    __shared__ unsigned long long sEZ[4][CHUNK];     // (ez, ez*z)
    __shared__ ulonglong2 sF[4][CHUNK * 2];          // ez*f packed as 4x f32x2

    int warp = threadIdx.x >> 5;
    int lane = threadIdx.x & 31;
    int t = blockIdx.x * 4 + warp;

    int b = t >> 12;                                 // / TILES_IMG (4096)
    int r = t & (TILES_IMG - 1);
    int ty = r >> 6;                                 // / TILES_X (64)
    int tx = r & (TILES_X - 1);

    int px  = tx * TW + (lane & (TW - 1));
    int py0 = ty * TH + (lane >> 3);                 // rows 0..3
    int py1 = py0 + 4;                               // rows 4..7

    float qxn  = NDC(px);
    float qyn0 = NDC(py0);
    float qyn1 = NDC(py1);

    float mr = __ldg(mr_ptr);
    float r2 = mr * mr;

    int cnt = g_cnt[t];
    if (cnt > CAP) cnt = CAP;

    const float4* ff = (const float4*)feat;

    float accWS0 = 0.f, accWS1 = 0.f;
    unsigned long long aW0 = 0ull, aW1 = 0ull;       // (accW, accWZ)
    unsigned long long p01 = 0ull, p23 = 0ull, p45 = 0ull, p67 = 0ull;
    unsigned long long q01 = 0ull, q23 = 0ull, q45 = 0ull, q67 = 0ull;

#define BODY(K)                                                               \
    {                                                                         \
        float4 A = sA[warp][(K)];                                             \
        unsigned long long ez2 = sEZ[warp][(K)];                              \
        ulonglong2 f01 = sF[warp][2 * (K) + 0];                               \
        ulonglong2 f23 = sF[warp][2 * (K) + 1];                               \
        float dx  = __fadd_rn(qxn, -A.x);                                     \
        float dx2 = __fmul_rn(dx, dx);                                        \
        float dy0 = __fadd_rn(qyn0, -A.y);                                    \
        float d20 = __fadd_rn(dx2, __fmul_rn(dy0, dy0));                      \
        float e0  = ex2(d20 * A.z);                                           \
        float ws0 = (d20 <= r2) ? e0 : 0.0f;                                  \
        accWS0 += ws0;                                                        \
        unsigned long long w20;                                               \
        asm("mov.b64 %0, {%1, %1};" : "=l"(w20) : "r"(__float_as_uint(ws0))); \
        ffma2(aW0, w20, ez2);                                                 \
        ffma2(p01, w20, f01.x);                                               \
        ffma2(p23, w20, f01.y);                                               \
        ffma2(p45, w20, f23.x);                                               \
        ffma2(p67, w20, f23.y);                                               \
        float dy1 = __fadd_rn(qyn1, -A.y);                                    \
        float d21 = __fadd_rn(dx2, __fmul_rn(dy1, dy1));                      \
        float e1  = ex2(d21 * A.z);                                           \
        float ws1 = (d21 <= r2) ? e1 : 0.0f;                                  \
        accWS1 += ws1;                                                        \
        unsigned long long w21;                                               \
        asm("mov.b64 %0, {%1, %1};" : "=l"(w21) : "r"(__float_as_uint(ws1))); \
        ffma2(aW1, w21, ez2);                                                 \
        ffma2(q01, w21, f01.x);                                               \
        ffma2(q23, w21, f01.y);                                               \
        ffma2(q45, w21, f23.x);                                               \
        ffma2(q67, w21, f23.y);                                               \
    }

    for (int c0 = 0; c0 < cnt; c0 += CHUNK) {
        int m = min(CHUNK, cnt - c0);
        if (lane < m) {
            int j = g_list[t * CAP + c0 + lane];
            float x = pts[3 * j + 0];
            float y = pts[3 * j + 1];
            float z = pts[3 * j + 2];
            float s = sig[j];
            // ex2 coefficient: -(1/(2 s^2)) * log2(e)  (ws = 2^(d2*coef))
            float coef = -(1.0f / (2.0f * s * s)) * LOG2E;
            float ez = __expf(-2.0f * z);            // GAMMA = 0.5
            sA[warp][lane] = make_float4(x, y, coef, 0.0f);
            sEZ[warp][lane] = pack2(ez, ez * z);
            float4 fa = ff[2 * j + 0];
            float4 fb = ff[2 * j + 1];
            sF[warp][2 * lane + 0] = make_ulonglong2(pack2(ez * fa.x, ez * fa.y),
                                                     pack2(ez * fa.z, ez * fa.w));
            sF[warp][2 * lane + 1] = make_ulonglong2(pack2(ez * fb.x, ez * fb.y),
                                                     pack2(ez * fb.z, ez * fb.w));
        }
        __syncwarp();

        if (m == CHUNK) {
            // Fully immediate LDS offsets.
#pragma unroll 8
            for (int k = 0; k < CHUNK; ++k) BODY(k);
        } else {
            // Stepped groups of 8: register base + immediate offsets.
            int k0 = 0;
            for (; k0 + 8 <= m; k0 += 8) {
#pragma unroll
                for (int u = 0; u < 8; ++u) BODY(k0 + u);
            }
            for (int k = k0; k < m; ++k) BODY(k);
        }
        __syncwarp();
    }
#undef BODY

    float4* col = (float4*)out;
    int pixbase = b * (HH * WW) + px;

    {   // pixel 0
        float accW, accWZ, f0, f1, f2, f3, f4v, f5, f6, f7;
        unpack2(aW0, accW, accWZ);
        unpack2(p01, f0, f1);  unpack2(p23, f2, f3);
        unpack2(p45, f4v, f5); unpack2(p67, f6, f7);
        int pix = pixbase + py0 * WW;
        float inv = (accW > 0.0f) ? (1.0f / accW) : 0.0f;
        col[2 * pix + 0] = make_float4(f0 * inv, f1 * inv, f2 * inv, f3 * inv);
        col[2 * pix + 1] = make_float4(f4v * inv, f5 * inv, f6 * inv, f7 * inv);
        out[NPIX * CC + pix]        = accWZ * inv;
        out[NPIX * CC + NPIX + pix] = 1.0f - expf(-accWS0);
    }
    {   // pixel 1
        float accW, accWZ, f0, f1, f2, f3, f4v, f5, f6, f7;
        unpack2(aW1, accW, accWZ);
        unpack2(q01, f0, f1);  unpack2(q23, f2, f3);
        unpack2(q45, f4v, f5); unpack2(q67, f6, f7);
        int pix = pixbase + py1 * WW;
        float inv = (accW > 0.0f) ? (1.0f / accW) : 0.0f;
        col[2 * pix + 0] = make_float4(f0 * inv, f1 * inv, f2 * inv, f3 * inv);
        col[2 * pix + 1] = make_float4(f4v * inv, f5 * inv, f6 * inv, f7 * inv);
        out[NPIX * CC + pix]        = accWZ * inv;
        out[NPIX * CC + NPIX + pix] = 1.0f - expf(-accWS1);
    }

    // Reset counter for next graph replay (all lanes of this warp already
    // read g_cnt[t] above).
    if (lane == 0) g_cnt[t] = 0;
}

// ---------------------------------------------------------------------------
extern "C" void kernel_launch(void* const* d_in, const int* in_sizes, int n_in,
                              void* d_out, int out_size) {
    const float* pts  = (const float*)d_in[0];  // [B,P,3]
    const float* feat = (const float*)d_in[1];  // [B,P,8]
    const float* sig  = (const float*)d_in[2];  // [B,P]
    const float* mr   = (const float*)d_in[3];  // scalar
    float* out = (float*)d_out;

    k_bin   <<<NPTS / 256, 256>>>(pts, mr);
    k_gather<<<NTILES / 4, 128>>>(pts, feat, sig, mr, out);
}